// round 1
// baseline (speedup 1.0000x reference)
#include <cuda_runtime.h>

#define LCOLS 4096
#define NSTAGES 12
#define RROWS 8
#define TPB 512
#define NBATCH 8192

// y[j] <- W[s][j][0]*y[j] + W[s][j][1]*y[j ^ (1<<s)]
// Thread t owns 8 contiguous columns [8t, 8t+8).
//   stages 0-2 : in-thread (partner col = c ^ d, d=1,2,4)
//   stages 3-7 : shfl_xor with lane mask d/8 (1,2,4,8,16)
//   stages 8-11: via shared memory, pairwise float4 updates
__global__ __launch_bounds__(TPB, 1)
void butterfly_kernel(const float* __restrict__ x,
                      const float* __restrict__ W,
                      float* __restrict__ out)
{
    extern __shared__ float sm[];   // RROWS * LCOLS floats = 128 KB
    const int tid  = threadIdx.x;
    const int row0 = blockIdx.x * RROWS;
    const int j0   = tid * 8;

    float y[RROWS][8];

    // ---- load 8 rows x 8 cols, vectorized & coalesced ----
    #pragma unroll
    for (int r = 0; r < RROWS; ++r) {
        const float4* p = reinterpret_cast<const float4*>(
            x + (size_t)(row0 + r) * LCOLS + j0);
        float4 a = __ldg(p);
        float4 b = __ldg(p + 1);
        y[r][0]=a.x; y[r][1]=a.y; y[r][2]=a.z; y[r][3]=a.w;
        y[r][4]=b.x; y[r][5]=b.y; y[r][6]=b.z; y[r][7]=b.w;
    }

    // ---- stages 0..7 : register / shuffle phase ----
    #pragma unroll
    for (int s = 0; s < 8; ++s) {
        // weights for my 8 cols at this stage: 16 contiguous floats
        float w0[8], w1[8];
        const float4* wp = reinterpret_cast<const float4*>(
            W + (size_t)s * (LCOLS * 2) + j0 * 2);
        float4 wA = __ldg(wp + 0), wB = __ldg(wp + 1);
        float4 wC = __ldg(wp + 2), wD = __ldg(wp + 3);
        w0[0]=wA.x; w1[0]=wA.y; w0[1]=wA.z; w1[1]=wA.w;
        w0[2]=wB.x; w1[2]=wB.y; w0[3]=wB.z; w1[3]=wB.w;
        w0[4]=wC.x; w1[4]=wC.y; w0[5]=wC.z; w1[5]=wC.w;
        w0[6]=wD.x; w1[6]=wD.y; w0[7]=wD.z; w1[7]=wD.w;

        if (s < 3) {
            const int d = 1 << s;                     // 1,2,4 : in-thread
            #pragma unroll
            for (int r = 0; r < RROWS; ++r) {
                float nt[8];
                #pragma unroll
                for (int c = 0; c < 8; ++c)
                    nt[c] = fmaf(w0[c], y[r][c], w1[c] * y[r][c ^ d]);
                #pragma unroll
                for (int c = 0; c < 8; ++c) y[r][c] = nt[c];
            }
        } else {
            const int m = 1 << (s - 3);               // lane xor 1..16
            #pragma unroll
            for (int r = 0; r < RROWS; ++r) {
                #pragma unroll
                for (int c = 0; c < 8; ++c) {
                    float p = __shfl_xor_sync(0xffffffffu, y[r][c], m);
                    y[r][c] = fmaf(w0[c], y[r][c], w1[c] * p);
                }
            }
        }
    }

    // ---- spill to shared for the long-stride stages ----
    #pragma unroll
    for (int r = 0; r < RROWS; ++r) {
        float4* sp = reinterpret_cast<float4*>(&sm[r * LCOLS + j0]);
        sp[0] = make_float4(y[r][0], y[r][1], y[r][2], y[r][3]);
        sp[1] = make_float4(y[r][4], y[r][5], y[r][6], y[r][7]);
    }
    __syncthreads();

    // ---- stages 8..11 : d = 256,512,1024,2048 via smem ----
    #pragma unroll
    for (int s = 8; s < 12; ++s) {
        const int d = 1 << s;
        const int i = tid * 4;                        // 4 pairs per thread per row
        const int top = ((i & ~(d - 1)) << 1) | (i & (d - 1));
        const int bot = top + d;

        const float4* wp = reinterpret_cast<const float4*>(
            W + (size_t)s * (LCOLS * 2) + top * 2);
        float4 wt0 = __ldg(wp), wt1 = __ldg(wp + 1);
        const float4* wq = reinterpret_cast<const float4*>(
            W + (size_t)s * (LCOLS * 2) + bot * 2);
        float4 wb0 = __ldg(wq), wb1 = __ldg(wq + 1);

        #pragma unroll
        for (int r = 0; r < RROWS; ++r) {
            float4 a = *reinterpret_cast<float4*>(&sm[r * LCOLS + top]);
            float4 b = *reinterpret_cast<float4*>(&sm[r * LCOLS + bot]);
            float4 na, nb;
            na.x = fmaf(wt0.x, a.x, wt0.y * b.x);
            na.y = fmaf(wt0.z, a.y, wt0.w * b.y);
            na.z = fmaf(wt1.x, a.z, wt1.y * b.z);
            na.w = fmaf(wt1.z, a.w, wt1.w * b.w);
            nb.x = fmaf(wb0.x, b.x, wb0.y * a.x);
            nb.y = fmaf(wb0.z, b.y, wb0.w * a.y);
            nb.z = fmaf(wb1.x, b.z, wb1.y * a.z);
            nb.w = fmaf(wb1.z, b.w, wb1.w * a.w);
            *reinterpret_cast<float4*>(&sm[r * LCOLS + top]) = na;
            *reinterpret_cast<float4*>(&sm[r * LCOLS + bot]) = nb;
        }
        __syncthreads();
    }

    // ---- write out, coalesced float4 ----
    #pragma unroll
    for (int r = 0; r < RROWS; ++r) {
        const float4* sp = reinterpret_cast<const float4*>(&sm[r * LCOLS + j0]);
        float4* op = reinterpret_cast<float4*>(
            out + (size_t)(row0 + r) * LCOLS + j0);
        op[0] = sp[0];
        op[1] = sp[1];
    }
}

extern "C" void kernel_launch(void* const* d_in, const int* in_sizes, int n_in,
                              void* d_out, int out_size) {
    // defensive input identification: W has 12*4096*2 = 98304 elements
    const float* x;
    const float* W;
    if (in_sizes[0] == NSTAGES * LCOLS * 2) {
        W = (const float*)d_in[0];
        x = (const float*)d_in[1];
    } else {
        x = (const float*)d_in[0];
        W = (const float*)d_in[1];
    }
    float* out = (float*)d_out;

    const int smem_bytes = RROWS * LCOLS * sizeof(float);  // 128 KB
    cudaFuncSetAttribute(butterfly_kernel,
                         cudaFuncAttributeMaxDynamicSharedMemorySize, smem_bytes);
    butterfly_kernel<<<NBATCH / RROWS, TPB, smem_bytes>>>(x, W, out);
}

// round 3
// speedup vs baseline: 1.4479x; 1.4479x over previous
#include <cuda_runtime.h>

#define LCOLS 4096
#define NSTAGES 12
#define RROWS 8
#define TPB 512
#define NBATCH 8192

// Swizzle: XOR bit4 with j's bit11, bit2 with j's bit5.
// Only touches bits >= 2, and bits 5/11 are constant within any 4-aligned
// group, so each float4 half stays contiguous (but the two halves of an
// 8-group may swap places -- handled explicitly at the store).
__device__ __forceinline__ int swz(int j) {
    return j ^ (((j >> 11) & 1) << 4) ^ (((j >> 5) & 1) << 2);
}

// y[j] <- W[s][j][0]*y[j] + W[s][j][1]*y[j ^ (1<<s)]
// Phase 1: thread owns 8 contiguous cols (bits 0-2 in-thread, bits 3-7 = lane -> shfl)
//          -> stages 0..7. One swizzled smem store.
// Phase 2: thread gathers j = b11*2048 + k*256 + low8 (k = bits 8-10 in-thread,
//          b11 = lane bit 0 -> shfl) -> stages 8..11. Direct global store.
__global__ __launch_bounds__(TPB, 1)
void butterfly_kernel(const float* __restrict__ x,
                      const float* __restrict__ W,
                      float* __restrict__ out)
{
    extern __shared__ float sm[];   // RROWS * LCOLS floats = 128 KB
    const int tid  = threadIdx.x;
    const int row0 = blockIdx.x * RROWS;
    const int j0   = tid * 8;

    float y[RROWS][8];

    // ---- load 8 rows x 8 cols, vectorized & coalesced ----
    #pragma unroll
    for (int r = 0; r < RROWS; ++r) {
        const float4* p = reinterpret_cast<const float4*>(
            x + (size_t)(row0 + r) * LCOLS + j0);
        float4 a = __ldg(p);
        float4 b = __ldg(p + 1);
        y[r][0]=a.x; y[r][1]=a.y; y[r][2]=a.z; y[r][3]=a.w;
        y[r][4]=b.x; y[r][5]=b.y; y[r][6]=b.z; y[r][7]=b.w;
    }

    // ---- phase 1: stages 0..7 (regs + shfl) ----
    #pragma unroll
    for (int s = 0; s < 8; ++s) {
        float w0[8], w1[8];
        const float4* wp = reinterpret_cast<const float4*>(
            W + (size_t)s * (LCOLS * 2) + j0 * 2);
        float4 wA = __ldg(wp + 0), wB = __ldg(wp + 1);
        float4 wC = __ldg(wp + 2), wD = __ldg(wp + 3);
        w0[0]=wA.x; w1[0]=wA.y; w0[1]=wA.z; w1[1]=wA.w;
        w0[2]=wB.x; w1[2]=wB.y; w0[3]=wB.z; w1[3]=wB.w;
        w0[4]=wC.x; w1[4]=wC.y; w0[5]=wC.z; w1[5]=wC.w;
        w0[6]=wD.x; w1[6]=wD.y; w0[7]=wD.z; w1[7]=wD.w;

        if (s < 3) {
            const int d = 1 << s;                     // 1,2,4 in-thread
            #pragma unroll
            for (int r = 0; r < RROWS; ++r) {
                float nt[8];
                #pragma unroll
                for (int c = 0; c < 8; ++c)
                    nt[c] = fmaf(w0[c], y[r][c], w1[c] * y[r][c ^ d]);
                #pragma unroll
                for (int c = 0; c < 8; ++c) y[r][c] = nt[c];
            }
        } else {
            const int m = 1 << (s - 3);               // lane xor 1..16
            #pragma unroll
            for (int r = 0; r < RROWS; ++r) {
                #pragma unroll
                for (int c = 0; c < 8; ++c) {
                    float p = __shfl_xor_sync(0xffffffffu, y[r][c], m);
                    y[r][c] = fmaf(w0[c], y[r][c], w1[c] * p);
                }
            }
        }
    }

    // ---- single swizzled smem store: element j lands at sm[swz(j)] ----
    {
        const int s0 = swz(j0);        // address of elements j0..j0+3
        const int s1 = swz(j0 + 4);    // address of elements j0+4..j0+7
        #pragma unroll
        for (int r = 0; r < RROWS; ++r) {
            *reinterpret_cast<float4*>(&sm[r * LCOLS + s0]) =
                make_float4(y[r][0], y[r][1], y[r][2], y[r][3]);
            *reinterpret_cast<float4*>(&sm[r * LCOLS + s1]) =
                make_float4(y[r][4], y[r][5], y[r][6], y[r][7]);
        }
    }
    __syncthreads();

    // ---- phase 2: stages 8..11 ----
    const int l     = tid & 31;
    const int w     = tid >> 5;
    const int b11   = l & 1;                 // stage-11 partner = lane^1
    const int low8  = (w << 4) | (l >> 1);   // bits 0..7 of j
    const int jbase = b11 * 2048 + low8;     // j(k) = jbase + k*256
    // swizzle offset constant per thread (bit5 of j = bit5 of low8; bit11 = b11)
    const int sjbase = jbase ^ (b11 << 4) ^ (((low8 >> 5) & 1) << 2);

    // weights for stages 8..11, 8 columns each, loaded once, reused for all rows
    float w0p[4][8], w1p[4][8];
    #pragma unroll
    for (int s4 = 0; s4 < 4; ++s4) {
        #pragma unroll
        for (int k = 0; k < 8; ++k) {
            const float2 ww = __ldg(reinterpret_cast<const float2*>(
                W + (size_t)(8 + s4) * (LCOLS * 2) + 2 * (jbase + k * 256)));
            w0p[s4][k] = ww.x;
            w1p[s4][k] = ww.y;
        }
    }

    #pragma unroll
    for (int r = 0; r < RROWS; ++r) {
        float v[8];
        #pragma unroll
        for (int k = 0; k < 8; ++k)
            v[k] = sm[r * LCOLS + sjbase + k * 256];   // conflict-free gather

        // stages 8,9,10 : butterflies on k bits 0,1,2
        #pragma unroll
        for (int sb = 0; sb < 3; ++sb) {
            const int d = 1 << sb;
            float nv[8];
            #pragma unroll
            for (int k = 0; k < 8; ++k)
                nv[k] = fmaf(w0p[sb][k], v[k], w1p[sb][k] * v[k ^ d]);
            #pragma unroll
            for (int k = 0; k < 8; ++k) v[k] = nv[k];
        }

        // stage 11 : partner is lane^1 (b11 flip)
        #pragma unroll
        for (int k = 0; k < 8; ++k) {
            float p = __shfl_xor_sync(0xffffffffu, v[k], 1);
            v[k] = fmaf(w0p[3][k], v[k], w1p[3][k] * p);
        }

        // direct global store (per k: warp covers 2 x 16 consecutive floats)
        float* op = out + (size_t)(row0 + r) * LCOLS + jbase;
        #pragma unroll
        for (int k = 0; k < 8; ++k)
            op[k * 256] = v[k];
    }
}

extern "C" void kernel_launch(void* const* d_in, const int* in_sizes, int n_in,
                              void* d_out, int out_size) {
    const float* x;
    const float* W;
    if (in_sizes[0] == NSTAGES * LCOLS * 2) {   // W has 98304 elements
        W = (const float*)d_in[0];
        x = (const float*)d_in[1];
    } else {
        x = (const float*)d_in[0];
        W = (const float*)d_in[1];
    }
    float* out = (float*)d_out;

    const int smem_bytes = RROWS * LCOLS * sizeof(float);  // 128 KB
    cudaFuncSetAttribute(butterfly_kernel,
                         cudaFuncAttributeMaxDynamicSharedMemorySize, smem_bytes);
    butterfly_kernel<<<NBATCH / RROWS, TPB, smem_bytes>>>(x, W, out);
}